// round 14
// baseline (speedup 1.0000x reference)
#include <cuda_runtime.h>

#define BATCH 4096
#define SEQ   200
#define EMB   128
#define VOCAB 100000

#define K1_BLOCKS 1184                 // 148 SMs x 8 CTAs -> single resident wave
#define K1_WARPS  (K1_BLOCKS * 8)      // 9472
#define GEMV_TASKS 12500               // 8 vocab rows per task, 12500*8 = 100000

// Scratch (zero-init at module load; slots >= cnt in CIDX are never written -> stay 0)
__device__ __align__(16) float Pbuf[VOCAB * 2];
__device__ __align__(16) int   CIDX[BATCH * SEQ];
__device__ int                 CNT[BATCH];

// ---- K1: compaction (first 4096 warps) + grid-strided GEMV P = emb @ W^T ----
__global__ __launch_bounds__(256)
void k1_precompute_compact(const float* __restrict__ emb,
                           const float* __restrict__ W,
                           const int* __restrict__ x)
{
    const int warp = threadIdx.x >> 5;
    const int lane = threadIdx.x & 31;
    const int wg   = blockIdx.x * 8 + warp;        // global warp id

    // --- Compaction: one warp per batch row (warps 0..4095) ---
    if (wg < BATCH) {
        const int* xr = x + wg * SEQ;
        int base = 0;
        #pragma unroll
        for (int c = 0; c < 7; c++) {
            int s   = 32 * c + lane;
            int idx = (s < SEQ) ? __ldg(&xr[s]) : -1;
            bool valid = (idx >= 0);
            unsigned bm = __ballot_sync(0xFFFFFFFFu, valid);
            if (valid)
                CIDX[wg * SEQ + base + __popc(bm & ((1u << lane) - 1u))] = idx;
            base += __popc(bm);
        }
        if (lane == 0) CNT[wg] = base;             // >= 1 (column 0 always valid)
    }

    // --- GEMV: 8 lanes per row, 8 rows per task, warp-level grid stride ---
    const int sub = lane & 7;
    const int grp = lane >> 3;

    const float4* emb4 = reinterpret_cast<const float4*>(emb);
    const float4* W4   = reinterpret_cast<const float4*>(W);

    float4 w0[4], w1[4];
    #pragma unroll
    for (int i = 0; i < 4; i++) {
        w0[i] = __ldg(&W4[sub + 8 * i]);
        w1[i] = __ldg(&W4[32 + sub + 8 * i]);
    }

    for (int t = wg; t < GEMV_TASKS; t += K1_WARPS) {
        const int row_base = t * 8;
        const int rA = row_base + grp;             // always < VOCAB (exact tiling)
        const int rB = row_base + 4 + grp;

        float4 eA[4], eB[4];
        #pragma unroll
        for (int i = 0; i < 4; i++) {
            eA[i] = __ldg(&emb4[rA * 32 + sub + 8 * i]);
            eB[i] = __ldg(&emb4[rB * 32 + sub + 8 * i]);
        }

        float dA0 = 0.f, dA1 = 0.f, dB0 = 0.f, dB1 = 0.f;
        #pragma unroll
        for (int i = 0; i < 4; i++) {
            dA0 += eA[i].x * w0[i].x + eA[i].y * w0[i].y + eA[i].z * w0[i].z + eA[i].w * w0[i].w;
            dA1 += eA[i].x * w1[i].x + eA[i].y * w1[i].y + eA[i].z * w1[i].z + eA[i].w * w1[i].w;
            dB0 += eB[i].x * w0[i].x + eB[i].y * w0[i].y + eB[i].z * w0[i].z + eB[i].w * w0[i].w;
            dB1 += eB[i].x * w1[i].x + eB[i].y * w1[i].y + eB[i].z * w1[i].z + eB[i].w * w1[i].w;
        }

        #pragma unroll
        for (int off = 4; off > 0; off >>= 1) {
            dA0 += __shfl_xor_sync(0xFFFFFFFFu, dA0, off);
            dA1 += __shfl_xor_sync(0xFFFFFFFFu, dA1, off);
            dB0 += __shfl_xor_sync(0xFFFFFFFFu, dB0, off);
            dB1 += __shfl_xor_sync(0xFFFFFFFFu, dB1, off);
        }

        if (sub == 0) {
            float2* P2 = reinterpret_cast<float2*>(Pbuf);
            P2[rA] = make_float2(dA0, dA1);
            P2[rB] = make_float2(dB0, dB1);
        }
    }
}

// ---- K2: one warp per row. 2 int4 idx loads, 8 independent L2 gathers (MLP=8). ----
__global__ __launch_bounds__(256)
void k2_gather(const float* __restrict__ bias,
               float* __restrict__ out)
{
    const int warp = threadIdx.x >> 5;
    const int lane = threadIdx.x & 31;
    const int row  = blockIdx.x * 8 + warp;        // 0..4095

    const int cnt = __ldg(&CNT[row]);
    const int4* cq = reinterpret_cast<const int4*>(CIDX + row * SEQ);
    const float2* P = reinterpret_cast<const float2*>(Pbuf);

    // Lanes 0..24 hold slots [4*lane, 4*lane+3] and [100+4*lane, 100+4*lane+3].
    const bool act = (lane < 25);
    int4 qa = act ? __ldg(&cq[lane])      : make_int4(0, 0, 0, 0);  // slots 0..99
    int4 qb = act ? __ldg(&cq[25 + lane]) : make_int4(0, 0, 0, 0);  // slots 100..199
    const int sA = act ? 4 * lane : 200;           // inactive lanes -> slot >= cnt
    const int sB = sA + 100;

    // 8 independent gathers, L2-only (__ldcg: skip L1 allocate).
    float2 p0 = __ldcg(&P[qa.x]);
    float2 p1 = __ldcg(&P[qa.y]);
    float2 p2 = __ldcg(&P[qa.z]);
    float2 p3 = __ldcg(&P[qa.w]);
    float2 p4 = __ldcg(&P[qb.x]);
    float2 p5 = __ldcg(&P[qb.y]);
    float2 p6 = __ldcg(&P[qb.z]);
    float2 p7 = __ldcg(&P[qb.w]);

    float m0 = (sA     < cnt) ? 1.f : 0.f;
    float m1 = (sA + 1 < cnt) ? 1.f : 0.f;
    float m2 = (sA + 2 < cnt) ? 1.f : 0.f;
    float m3 = (sA + 3 < cnt) ? 1.f : 0.f;
    float m4 = (sB     < cnt) ? 1.f : 0.f;
    float m5 = (sB + 1 < cnt) ? 1.f : 0.f;
    float m6 = (sB + 2 < cnt) ? 1.f : 0.f;
    float m7 = (sB + 3 < cnt) ? 1.f : 0.f;

    float a0 = m0*p0.x + m1*p1.x + m2*p2.x + m3*p3.x
             + m4*p4.x + m5*p5.x + m6*p6.x + m7*p7.x;
    float a1 = m0*p0.y + m1*p1.y + m2*p2.y + m3*p3.y
             + m4*p4.y + m5*p5.y + m6*p6.y + m7*p7.y;

    #pragma unroll
    for (int off = 16; off > 0; off >>= 1) {
        a0 += __shfl_xor_sync(0xFFFFFFFFu, a0, off);
        a1 += __shfl_xor_sync(0xFFFFFFFFu, a1, off);
    }

    if (lane == 0) {
        float inv = 1.0f / (float)cnt;             // cnt >= 1
        out[row * 2 + 0] = a0 * inv + bias[0];
        out[row * 2 + 1] = a1 * inv + bias[1];
    }
}

extern "C" void kernel_launch(void* const* d_in, const int* in_sizes, int n_in,
                              void* d_out, int out_size)
{
    const int* x     = (const int*)d_in[0];       // int32 [4096,200]
    const float* emb = (const float*)d_in[1];     // [100000,128]
    const float* W   = (const float*)d_in[2];     // [2,128]
    const float* b   = (const float*)d_in[3];     // [2]
    float* out       = (float*)d_out;             // [4096,2]

    k1_precompute_compact<<<K1_BLOCKS, 256>>>(emb, W, x);
    k2_gather<<<BATCH / 8, 256>>>(b, out);        // 512 CTAs, 1 warp per row
}

// round 15
// speedup vs baseline: 1.2765x; 1.2765x over previous
#include <cuda_runtime.h>
#include <cstdint>

#define BATCH 4096
#define SEQ   200
#define EMB   128
#define VOCAB 100000
#define NPRE  1563            // ceil(100000 / 64) precompute blocks
#define NCMP  512             // 512 blocks * 8 warps = 4096 rows compacted

// Scratch (recomputed every launch; CIDX slots >= cnt hold old-launch or zero values,
// always in-bounds vocab indices, and are masked out of the reduction).
__device__ __align__(16) float Pbuf[VOCAB * 2];
__device__ __align__(16) int   CIDX[BATCH * SEQ];
__device__ int                 CNT[BATCH];

__device__ __forceinline__ void cpa8(uint32_t smem_dst, const void* gsrc) {
    asm volatile("cp.async.ca.shared.global [%0], [%1], 8;"
                 :: "r"(smem_dst), "l"(gsrc));
}

// ---- K1: heterogeneous. Blocks <NPRE: P = emb @ W^T. Blocks >=NPRE: compact indices. ----
__global__ __launch_bounds__(256)
void k1_precompute_compact(const float* __restrict__ emb,
                           const float* __restrict__ W,
                           const int* __restrict__ x)
{
    const int warp = threadIdx.x >> 5;
    const int lane = threadIdx.x & 31;

    if (blockIdx.x < NPRE) {
        const int warp_g = blockIdx.x * 8 + warp;
        const int sub = lane & 7;
        const int grp = lane >> 3;
        const int row_base = warp_g * 8;
        if (row_base >= VOCAB) return;

        const float4* emb4 = reinterpret_cast<const float4*>(emb);
        const float4* W4   = reinterpret_cast<const float4*>(W);

        float4 w0[4], w1[4];
        #pragma unroll
        for (int i = 0; i < 4; i++) {
            w0[i] = __ldg(&W4[sub + 8 * i]);
            w1[i] = __ldg(&W4[32 + sub + 8 * i]);
        }

        int rA = row_base + grp;
        int rB = row_base + 4 + grp;
        int cA = (rA < VOCAB) ? rA : VOCAB - 1;
        int cB = (rB < VOCAB) ? rB : VOCAB - 1;

        float4 eA[4], eB[4];
        #pragma unroll
        for (int i = 0; i < 4; i++) {
            eA[i] = __ldg(&emb4[cA * 32 + sub + 8 * i]);
            eB[i] = __ldg(&emb4[cB * 32 + sub + 8 * i]);
        }

        float dA0 = 0.f, dA1 = 0.f, dB0 = 0.f, dB1 = 0.f;
        #pragma unroll
        for (int i = 0; i < 4; i++) {
            dA0 += eA[i].x * w0[i].x + eA[i].y * w0[i].y + eA[i].z * w0[i].z + eA[i].w * w0[i].w;
            dA1 += eA[i].x * w1[i].x + eA[i].y * w1[i].y + eA[i].z * w1[i].z + eA[i].w * w1[i].w;
            dB0 += eB[i].x * w0[i].x + eB[i].y * w0[i].y + eB[i].z * w0[i].z + eB[i].w * w0[i].w;
            dB1 += eB[i].x * w1[i].x + eB[i].y * w1[i].y + eB[i].z * w1[i].z + eB[i].w * w1[i].w;
        }

        #pragma unroll
        for (int off = 4; off > 0; off >>= 1) {
            dA0 += __shfl_xor_sync(0xFFFFFFFFu, dA0, off);
            dA1 += __shfl_xor_sync(0xFFFFFFFFu, dA1, off);
            dB0 += __shfl_xor_sync(0xFFFFFFFFu, dB0, off);
            dB1 += __shfl_xor_sync(0xFFFFFFFFu, dB1, off);
        }

        if (sub == 0) {
            float2* P2 = reinterpret_cast<float2*>(Pbuf);
            if (rA < VOCAB) P2[rA] = make_float2(dA0, dA1);
            if (rB < VOCAB) P2[rB] = make_float2(dB0, dB1);
        }
    } else {
        const int row = (blockIdx.x - NPRE) * 8 + warp;
        const int* xr = x + row * SEQ;
        int base = 0;
        #pragma unroll
        for (int c = 0; c < 7; c++) {
            int s   = 32 * c + lane;
            int idx = (s < SEQ) ? __ldg(&xr[s]) : -1;
            bool valid = (idx >= 0);
            unsigned bm = __ballot_sync(0xFFFFFFFFu, valid);
            if (valid)
                CIDX[row * SEQ + base + __popc(bm & ((1u << lane) - 1u))] = idx;
            base += __popc(bm);
        }
        if (lane == 0) CNT[row] = base;     // >= 1 (column 0 always valid)
    }
}

// ---- K2: cp.async-staged gathers. 2 warps per row, 100 slots per warp. ----
__global__ __launch_bounds__(256)
void k2_gather(const float* __restrict__ bias,
               float* __restrict__ out)
{
    const int tid    = threadIdx.x;
    const int warp   = tid >> 5;            // 0..7
    const int lane   = tid & 31;
    const int warp_g = blockIdx.x * 8 + warp;
    const int row    = warp_g >> 1;         // 4 rows per block
    const int half   = warp_g & 1;

    __shared__ __align__(16) float2 stage[8][100];   // 6400B staged P entries
    __shared__ __align__(16) float2 part[8];
    __shared__ int scnt[4];

    const float2* P = reinterpret_cast<const float2*>(Pbuf);
    const int cnt = __ldg(&CNT[row]);
    const int4* cq = reinterpret_cast<const int4*>(CIDX + row * SEQ);

    const uint32_t sbase = (uint32_t)__cvta_generic_to_shared(&stage[warp][0]);

    // Lanes 0..24: load 4 compacted indices (one int4) and issue 4 async 8B gathers
    // into SMEM. No per-warp MSHR pressure: LDGSTS depth is uncapped.
    if (lane < 25) {
        int4 q = __ldg(&cq[half * 25 + lane]);       // slots 4*lane .. 4*lane+3
        int c0 = min(max(q.x, 0), VOCAB - 1);
        int c1 = min(max(q.y, 0), VOCAB - 1);
        int c2 = min(max(q.z, 0), VOCAB - 1);
        int c3 = min(max(q.w, 0), VOCAB - 1);
        uint32_t d = sbase + (uint32_t)(4 * lane) * 8u;
        cpa8(d,      &P[c0]);
        cpa8(d + 8,  &P[c1]);
        cpa8(d + 16, &P[c2]);
        cpa8(d + 24, &P[c3]);
    }
    asm volatile("cp.async.commit_group;" ::: "memory");
    asm volatile("cp.async.wait_group 0;" ::: "memory");
    __syncwarp();

    // Conflict-free readback: lane reads slots lane, lane+32, lane+64 (+96 for lanes 0..3).
    float2 p0 = stage[warp][lane];
    float2 p1 = stage[warp][lane + 32];
    float2 p2 = stage[warp][lane + 64];
    float2 p3 = (lane < 4) ? stage[warp][96 + lane] : make_float2(0.f, 0.f);

    const int g = half * 100;               // global slot base for this half
    float m0 = (g + lane       < cnt) ? 1.f : 0.f;
    float m1 = (g + lane + 32  < cnt) ? 1.f : 0.f;
    float m2 = (g + lane + 64  < cnt) ? 1.f : 0.f;
    float m3 = (lane < 4 && g + 96 + lane < cnt) ? 1.f : 0.f;

    float a0 = m0 * p0.x + m1 * p1.x + m2 * p2.x + m3 * p3.x;
    float a1 = m0 * p0.y + m1 * p1.y + m2 * p2.y + m3 * p3.y;

    #pragma unroll
    for (int off = 16; off > 0; off >>= 1) {
        a0 += __shfl_xor_sync(0xFFFFFFFFu, a0, off);
        a1 += __shfl_xor_sync(0xFFFFFFFFu, a1, off);
    }

    if (lane == 0) {
        part[warp] = make_float2(a0, a1);
        if (half == 0) scnt[warp >> 1] = cnt;
    }
    __syncthreads();

    // 4 rows per block: thread t < 4 combines halves of row blockIdx.x*4 + t.
    if (tid < 4) {
        float2 h0 = part[2 * tid];
        float2 h1 = part[2 * tid + 1];
        float inv = 1.0f / (float)scnt[tid];     // cnt >= 1
        int r = blockIdx.x * 4 + tid;
        out[r * 2 + 0] = (h0.x + h1.x) * inv + bias[0];
        out[r * 2 + 1] = (h0.y + h1.y) * inv + bias[1];
    }
}

extern "C" void kernel_launch(void* const* d_in, const int* in_sizes, int n_in,
                              void* d_out, int out_size)
{
    const int* x     = (const int*)d_in[0];       // int32 [4096,200]
    const float* emb = (const float*)d_in[1];     // [100000,128]
    const float* W   = (const float*)d_in[2];     // [2,128]
    const float* b   = (const float*)d_in[3];     // [2]
    float* out       = (float*)d_out;             // [4096,2]

    k1_precompute_compact<<<NPRE + NCMP, 256>>>(emb, W, x);
    k2_gather<<<BATCH / 4, 256>>>(b, out);
}